// round 5
// baseline (speedup 1.0000x reference)
#include <cuda_runtime.h>

#define NB 8
#define NN 10000
#define CI 16
#define TT 24
#define CO 32
#define NE 160000
#define BT 192   // NB*TT

// ---------------- device scratch (float4-typed => guaranteed 16B alignment) ----------------
__device__ float4 g_X0[(size_t)NN * BT * CI / 4];   // 122.88 MB  node-major layer-1 input
__device__ float4 g_Y1[(size_t)NN * BT * CO / 4];   // 245.76 MB  layer-1 output
__device__ int    g_cur[NN];
__device__ int    g_rowptr[NN + 1];
__device__ int    g_col[NE];
__device__ int    g_is64;   // 1 if edge_index buffer is int64, 0 if int32

// ---------------- packed f32x2 helpers ----------------
__device__ __forceinline__ unsigned long long fma2(unsigned long long a,
                                                   unsigned long long b,
                                                   unsigned long long c) {
    unsigned long long d;
    asm("fma.rn.f32x2 %0, %1, %2, %3;" : "=l"(d) : "l"(a), "l"(b), "l"(c));
    return d;
}
__device__ __forceinline__ unsigned long long pk2(float x, float y) {
    unsigned long long r;
    asm("mov.b64 %0, {%1, %2};" : "=l"(r) : "f"(x), "f"(y));
    return r;
}
__device__ __forceinline__ float2 upk2(unsigned long long a) {
    float2 r;
    asm("mov.b64 {%0, %1}, %2;" : "=f"(r.x), "=f"(r.y) : "l"(a));
    return r;
}

__device__ __forceinline__ int edge_at(const void* ei, int idx) {
    if (g_is64) return (int)((const long long*)ei)[idx];
    return ((const int*)ei)[idx];
}

// ---------------- CSR prep: dtype detect + degree histogram + scan, one block ----------------
__global__ void __launch_bounds__(1024) k_prep(const void* ei) {
    __shared__ int sdeg[NN];    // 40 KB
    __shared__ int ssum[1024];  //  4 KB
    int tid = threadIdx.x;
    if (tid == 0) {  // int64 indices are all in [0,NN); int32-reinterpreted are not
        const long long* p = (const long long*)ei;
        int ok64 = 1;
        for (int q = 0; q < 64; q++) {
            long long v = p[q];
            if (v < 0 || v >= NN) { ok64 = 0; break; }
        }
        g_is64 = ok64;
    }
    __syncthreads();
    for (int i = tid; i < NN; i += 1024) sdeg[i] = 0;
    __syncthreads();
    for (int e = tid; e < NE; e += 1024) atomicAdd(&sdeg[edge_at(ei, NE + e)], 1);
    __syncthreads();
    const int CHUNK = 10;  // 1024*10 >= NN
    int start = tid * CHUNK;
    int s = 0;
    for (int i = start; i < start + CHUNK && i < NN; i++) s += sdeg[i];
    ssum[tid] = s;
    __syncthreads();
    for (int off = 1; off < 1024; off <<= 1) {
        int v = (tid >= off) ? ssum[tid - off] : 0;
        __syncthreads();
        ssum[tid] += v;
        __syncthreads();
    }
    int run = ssum[tid] - s;  // exclusive prefix
    for (int i = start; i < start + CHUNK && i < NN; i++) {
        g_rowptr[i] = run;
        g_cur[i] = 0;
        run += sdeg[i];
    }
    if (tid == 1023) g_rowptr[NN] = ssum[1023];
}

__global__ void k_fill(const void* __restrict__ ei) {
    int e = blockIdx.x * blockDim.x + threadIdx.x;
    if (e < NE) {
        int srcn = edge_at(ei, e);
        int d    = edge_at(ei, NE + e);
        int p = atomicAdd(&g_cur[d], 1);
        g_col[g_rowptr[d] + p] = srcn;
    }
}

// ---------------- input transpose: x[b][n][c][t] -> X0[n][b*T+t][c] ----------------
__global__ void k_transpose(const float* __restrict__ x) {
    __shared__ float s[BT * 17];
    int n = blockIdx.x;
    for (int j = threadIdx.x; j < NB * CI * TT; j += blockDim.x) {
        int b = j / (CI * TT);
        int r = j % (CI * TT);
        int c = r / TT;
        int t = r % TT;
        s[(b * TT + t) * 17 + c] = x[((size_t)(b * NN + n)) * (CI * TT) + r];
    }
    __syncthreads();
    float* X0f = (float*)g_X0;
    for (int j = threadIdx.x; j < BT * CI; j += blockDim.x) {
        X0f[(size_t)n * (BT * CI) + j] = s[(j >> 4) * 17 + (j & 15)];
    }
}

// ---------------- layer 1: grid (NN, 2), 96 thr, 1 row/thread, bt-chunked for L2 ----------------
__global__ void __launch_bounds__(96) k_layer1(const float* __restrict__ W1,
                                               const float* __restrict__ b1,
                                               const float* __restrict__ W2,
                                               const float* __restrict__ b2) {
    __shared__ __align__(16) float sW1[CI * 64];
    __shared__ __align__(16) float sW2[64 * CO];
    __shared__ __align__(16) float sb1[64];
    __shared__ __align__(16) float sb2[CO];

    int n = blockIdx.x, tid = threadIdx.x;
    int r = blockIdx.y * 96 + tid;  // row within BT
    for (int i = tid; i < CI * 64; i += 96) sW1[i] = W1[i];
    for (int i = tid; i < 64 * CO; i += 96) sW2[i] = W2[i];
    if (tid < 64) sb1[tid] = b1[tid];
    if (tid < CO) sb2[tid] = b2[tid];

    // gather row r of node n + all its sources (row = 4 float4)
    const float4* X4 = g_X0;
    float4 a[4];
#pragma unroll
    for (int q = 0; q < 4; q++) a[q] = X4[((size_t)n * BT + r) * 4 + q];
    int rs = g_rowptr[n], re = g_rowptr[n + 1];
    for (int e = rs; e < re; e++) {
        size_t sb = ((size_t)g_col[e] * BT + r) * 4;
#pragma unroll
        for (int q = 0; q < 4; q++) {
            float4 v = X4[sb + q];
            a[q].x += v.x; a[q].y += v.y; a[q].z += v.z; a[q].w += v.w;
        }
    }
    __syncthreads();  // weights staged

    unsigned long long xp[CI];
#pragma unroll
    for (int q = 0; q < 4; q++) {
        xp[4 * q + 0] = pk2(a[q].x, a[q].x);
        xp[4 * q + 1] = pk2(a[q].y, a[q].y);
        xp[4 * q + 2] = pk2(a[q].z, a[q].z);
        xp[4 * q + 3] = pk2(a[q].w, a[q].w);
    }
    unsigned long long oa[16];
    const ulonglong2* bb = (const ulonglong2*)sb2;
#pragma unroll
    for (int i = 0; i < 8; i++) { ulonglong2 t2 = bb[i]; oa[2 * i] = t2.x; oa[2 * i + 1] = t2.y; }

#pragma unroll 1
    for (int j4 = 0; j4 < 64; j4 += 4) {
        ulonglong2 hb = *(const ulonglong2*)&sb1[j4];
        unsigned long long h01 = hb.x, h23 = hb.y;
#pragma unroll
        for (int k = 0; k < CI; k++) {
            ulonglong2 w = *(const ulonglong2*)&sW1[k * 64 + j4];
            h01 = fma2(xp[k], w.x, h01);
            h23 = fma2(xp[k], w.y, h23);
        }
        float2 p0 = upk2(h01), p1 = upk2(h23);
        float hv[4] = {fmaxf(p0.x, 0.f), fmaxf(p0.y, 0.f), fmaxf(p1.x, 0.f), fmaxf(p1.y, 0.f)};
#pragma unroll
        for (int hh = 0; hh < 4; hh++) {
            unsigned long long hp = pk2(hv[hh], hv[hh]);
            const ulonglong2* wr = (const ulonglong2*)&sW2[(j4 + hh) * CO];
#pragma unroll
            for (int i = 0; i < 8; i++) {
                ulonglong2 w = wr[i];
                oa[2 * i]     = fma2(hp, w.x, oa[2 * i]);
                oa[2 * i + 1] = fma2(hp, w.y, oa[2 * i + 1]);
            }
        }
    }
    float4* dst = &g_Y1[((size_t)n * BT + r) * 8];
#pragma unroll
    for (int q = 0; q < 8; q++) {
        float2 lo = upk2(oa[2 * q]), hi = upk2(oa[2 * q + 1]);
        dst[q] = make_float4(lo.x, lo.y, hi.x, hi.y);
    }
}

// ---------------- layer 2: grid (NN, 3), 64 thr, 1 row/thread, bt-chunked for L2 ----------------
__global__ void __launch_bounds__(64) k_layer2(const float* __restrict__ W3,
                                               const float* __restrict__ b3,
                                               const float* __restrict__ W4,
                                               const float* __restrict__ b4,
                                               float* __restrict__ out) {
    __shared__ __align__(16) float sW3[CO * 128];
    __shared__ __align__(16) float sW4[128 * CO];
    __shared__ __align__(16) float sb3[128];
    __shared__ __align__(16) float sb4[CO];

    int n = blockIdx.x, tid = threadIdx.x;
    int r = blockIdx.y * 64 + tid;  // row within BT
    for (int i = tid; i < CO * 128; i += 64) sW3[i] = W3[i];
    for (int i = tid; i < 128 * CO; i += 64) sW4[i] = W4[i];
    if (tid < 64) { sb3[tid] = b3[tid]; sb3[64 + tid] = b3[64 + tid]; }
    if (tid < CO) sb4[tid] = b4[tid];

    // gather row r of node n + all sources (row = 8 float4)
    const float4* Y4 = g_Y1;
    float4 a[8];
#pragma unroll
    for (int q = 0; q < 8; q++) a[q] = Y4[((size_t)n * BT + r) * 8 + q];
    int rs = g_rowptr[n], re = g_rowptr[n + 1];
    for (int e = rs; e < re; e++) {
        size_t sb = ((size_t)g_col[e] * BT + r) * 8;
#pragma unroll
        for (int q = 0; q < 8; q++) {
            float4 v = Y4[sb + q];
            a[q].x += v.x; a[q].y += v.y; a[q].z += v.z; a[q].w += v.w;
        }
    }
    float xv[CO];
#pragma unroll
    for (int q = 0; q < 8; q++) {
        xv[4 * q + 0] = a[q].x; xv[4 * q + 1] = a[q].y;
        xv[4 * q + 2] = a[q].z; xv[4 * q + 3] = a[q].w;
    }
    __syncthreads();  // weights staged

    unsigned long long oa[16];
    const ulonglong2* bb = (const ulonglong2*)sb4;
#pragma unroll
    for (int i = 0; i < 8; i++) { ulonglong2 t2 = bb[i]; oa[2 * i] = t2.x; oa[2 * i + 1] = t2.y; }

#pragma unroll 1
    for (int j4 = 0; j4 < 128; j4 += 4) {
        ulonglong2 hb = *(const ulonglong2*)&sb3[j4];
        unsigned long long h01 = hb.x, h23 = hb.y;
#pragma unroll
        for (int k = 0; k < CO; k++) {
            ulonglong2 w = *(const ulonglong2*)&sW3[k * 128 + j4];
            unsigned long long xp = pk2(xv[k], xv[k]);
            h01 = fma2(xp, w.x, h01);
            h23 = fma2(xp, w.y, h23);
        }
        float2 p0 = upk2(h01), p1 = upk2(h23);
        float hv[4] = {fmaxf(p0.x, 0.f), fmaxf(p0.y, 0.f), fmaxf(p1.x, 0.f), fmaxf(p1.y, 0.f)};
#pragma unroll
        for (int hh = 0; hh < 4; hh++) {
            unsigned long long hp = pk2(hv[hh], hv[hh]);
            const ulonglong2* wr = (const ulonglong2*)&sW4[(j4 + hh) * CO];
#pragma unroll
            for (int i = 0; i < 8; i++) {
                ulonglong2 w = wr[i];
                oa[2 * i]     = fma2(hp, w.x, oa[2 * i]);
                oa[2 * i + 1] = fma2(hp, w.y, oa[2 * i + 1]);
            }
        }
    }

    // final relu + direct transposed write: row r -> (b = r/24, t = r%24)
    int b = r / TT, t = r % TT;
    size_t obase = ((size_t)(b * NN + n) * CO) * TT + t;
#pragma unroll
    for (int q = 0; q < 16; q++) {
        float2 p = upk2(oa[q]);
        out[obase + (size_t)(2 * q) * TT]     = fmaxf(p.x, 0.f);
        out[obase + (size_t)(2 * q + 1) * TT] = fmaxf(p.y, 0.f);
    }
}

// ---------------- launch ----------------
extern "C" void kernel_launch(void* const* d_in, const int* in_sizes, int n_in,
                              void* d_out, int out_size) {
    const float* x  = (const float*)d_in[0];
    const void*  ei = d_in[1];
    const float* W1 = (const float*)d_in[2];
    const float* b1 = (const float*)d_in[3];
    const float* W2 = (const float*)d_in[4];
    const float* b2 = (const float*)d_in[5];
    const float* W3 = (const float*)d_in[6];
    const float* b3 = (const float*)d_in[7];
    const float* W4 = (const float*)d_in[8];
    const float* b4 = (const float*)d_in[9];
    float* out = (float*)d_out;

    k_prep<<<1, 1024>>>(ei);
    k_fill<<<(NE + 255) / 256, 256>>>(ei);
    k_transpose<<<NN, 256>>>(x);
    k_layer1<<<dim3(NN, 2), 96>>>(W1, b1, W2, b2);
    k_layer2<<<dim3(NN, 3), 64>>>(W3, b3, W4, b4, out);
}

// round 6
// speedup vs baseline: 1.1730x; 1.1730x over previous
#include <cuda_runtime.h>

#define NB 8
#define NN 10000
#define CI 16
#define TT 24
#define CO 32
#define NE 160000
#define BT 192   // NB*TT

// ---------------- device scratch (float4-typed => guaranteed 16B alignment) ----------------
__device__ float4 g_X0[(size_t)NN * BT * CI / 4];   // 122.88 MB  node-major layer-1 input
__device__ float4 g_Y1[(size_t)NN * BT * CO / 4];   // 245.76 MB  layer-1 output
__device__ int    g_cur[NN];
__device__ int    g_rowptr[NN + 1];
__device__ int    g_col[NE];
__device__ int    g_is64;   // 1 if edge_index buffer is int64, 0 if int32

// ---------------- packed f32x2 helpers ----------------
__device__ __forceinline__ unsigned long long fma2(unsigned long long a,
                                                   unsigned long long b,
                                                   unsigned long long c) {
    unsigned long long d;
    asm("fma.rn.f32x2 %0, %1, %2, %3;" : "=l"(d) : "l"(a), "l"(b), "l"(c));
    return d;
}
__device__ __forceinline__ unsigned long long pk2(float x, float y) {
    unsigned long long r;
    asm("mov.b64 %0, {%1, %2};" : "=l"(r) : "f"(x), "f"(y));
    return r;
}
__device__ __forceinline__ float2 upk2(unsigned long long a) {
    float2 r;
    asm("mov.b64 {%0, %1}, %2;" : "=f"(r.x), "=f"(r.y) : "l"(a));
    return r;
}

__device__ __forceinline__ int edge_at(const void* ei, int idx) {
    if (g_is64) return (int)((const long long*)ei)[idx];
    return ((const int*)ei)[idx];
}

// ---------------- CSR prep: dtype detect + degree histogram + scan, one block ----------------
__global__ void __launch_bounds__(1024) k_prep(const void* ei) {
    __shared__ int sdeg[NN];    // 40 KB
    __shared__ int ssum[1024];  //  4 KB
    int tid = threadIdx.x;
    if (tid == 0) {  // int64 indices are all in [0,NN); int32-reinterpreted are not
        const long long* p = (const long long*)ei;
        int ok64 = 1;
        for (int q = 0; q < 64; q++) {
            long long v = p[q];
            if (v < 0 || v >= NN) { ok64 = 0; break; }
        }
        g_is64 = ok64;
    }
    __syncthreads();
    for (int i = tid; i < NN; i += 1024) sdeg[i] = 0;
    __syncthreads();
    for (int e = tid; e < NE; e += 1024) atomicAdd(&sdeg[edge_at(ei, NE + e)], 1);
    __syncthreads();
    const int CHUNK = 10;  // 1024*10 >= NN
    int start = tid * CHUNK;
    int s = 0;
    for (int i = start; i < start + CHUNK && i < NN; i++) s += sdeg[i];
    ssum[tid] = s;
    __syncthreads();
    for (int off = 1; off < 1024; off <<= 1) {
        int v = (tid >= off) ? ssum[tid - off] : 0;
        __syncthreads();
        ssum[tid] += v;
        __syncthreads();
    }
    int run = ssum[tid] - s;  // exclusive prefix
    for (int i = start; i < start + CHUNK && i < NN; i++) {
        g_rowptr[i] = run;
        g_cur[i] = 0;
        run += sdeg[i];
    }
    if (tid == 1023) g_rowptr[NN] = ssum[1023];
}

__global__ void k_fill(const void* __restrict__ ei) {
    int e = blockIdx.x * blockDim.x + threadIdx.x;
    if (e < NE) {
        int srcn = edge_at(ei, e);
        int d    = edge_at(ei, NE + e);
        int p = atomicAdd(&g_cur[d], 1);
        g_col[g_rowptr[d] + p] = srcn;
    }
}

// ---------------- input transpose: x[b][n][c][t] -> X0[n][b*T+t][c] ----------------
__global__ void k_transpose(const float* __restrict__ x) {
    __shared__ float s[BT * 17];
    int n = blockIdx.x;
    for (int j = threadIdx.x; j < NB * CI * TT; j += blockDim.x) {
        int b = j / (CI * TT);
        int r = j % (CI * TT);
        int c = r / TT;
        int t = r % TT;
        s[(b * TT + t) * 17 + c] = x[((size_t)(b * NN + n)) * (CI * TT) + r];
    }
    __syncthreads();
    float* X0f = (float*)g_X0;
    for (int j = threadIdx.x; j < BT * CI; j += blockDim.x) {
        X0f[(size_t)n * (BT * CI) + j] = s[(j >> 4) * 17 + (j & 15)];
    }
}

// ---------------- layer 1: agg + MLP(16->64 relu ->32); 96 thr, 2 rows/thread ----------------
__global__ void __launch_bounds__(96) k_layer1(const float* __restrict__ W1,
                                               const float* __restrict__ b1,
                                               const float* __restrict__ W2,
                                               const float* __restrict__ b2) {
    __shared__ __align__(16) float sW1[CI * 64];
    __shared__ __align__(16) float sW2[64 * CO];
    __shared__ __align__(16) float sb1[64];
    __shared__ __align__(16) float sb2[CO];

    int n = blockIdx.x, tid = threadIdx.x;
    {
        const float4* W1v = (const float4*)W1;
        const float4* W2v = (const float4*)W2;
        for (int i = tid; i < CI * 16; i += 96) ((float4*)sW1)[i] = W1v[i];
        for (int i = tid; i < 16 * CO; i += 96) ((float4*)sW2)[i] = W2v[i];
        if (tid < 64) sb1[tid] = b1[tid];
        if (tid < CO) sb2[tid] = b2[tid];
    }

    // gather rows r0=tid, r1=tid+96 directly into registers (row = 4 float4)
    const float4* X4 = g_X0;
    size_t base = (size_t)n * 768;
    float4 a0[4], a1[4];
#pragma unroll
    for (int q = 0; q < 4; q++) {
        a0[q] = X4[base + (size_t)tid * 4 + q];
        a1[q] = X4[base + (size_t)(tid + 96) * 4 + q];
    }
    int rs = g_rowptr[n], re = g_rowptr[n + 1];
    for (int e = rs; e < re; e++) {
        size_t sb = (size_t)g_col[e] * 768;
#pragma unroll
        for (int q = 0; q < 4; q++) {
            float4 v0 = X4[sb + (size_t)tid * 4 + q];
            float4 v1 = X4[sb + (size_t)(tid + 96) * 4 + q];
            a0[q].x += v0.x; a0[q].y += v0.y; a0[q].z += v0.z; a0[q].w += v0.w;
            a1[q].x += v1.x; a1[q].y += v1.y; a1[q].z += v1.z; a1[q].w += v1.w;
        }
    }
    __syncthreads();  // weights staged

    unsigned long long xp0[CI], xp1[CI];
#pragma unroll
    for (int q = 0; q < 4; q++) {
        xp0[4 * q + 0] = pk2(a0[q].x, a0[q].x);
        xp0[4 * q + 1] = pk2(a0[q].y, a0[q].y);
        xp0[4 * q + 2] = pk2(a0[q].z, a0[q].z);
        xp0[4 * q + 3] = pk2(a0[q].w, a0[q].w);
        xp1[4 * q + 0] = pk2(a1[q].x, a1[q].x);
        xp1[4 * q + 1] = pk2(a1[q].y, a1[q].y);
        xp1[4 * q + 2] = pk2(a1[q].z, a1[q].z);
        xp1[4 * q + 3] = pk2(a1[q].w, a1[q].w);
    }

    unsigned long long oa0[16], oa1[16];
    const ulonglong2* bb = (const ulonglong2*)sb2;
#pragma unroll
    for (int i = 0; i < 8; i++) {
        ulonglong2 t2 = bb[i];
        oa0[2 * i] = t2.x; oa0[2 * i + 1] = t2.y;
        oa1[2 * i] = t2.x; oa1[2 * i + 1] = t2.y;
    }

#pragma unroll 1
    for (int j4 = 0; j4 < 64; j4 += 4) {
        ulonglong2 hb = *(const ulonglong2*)&sb1[j4];
        unsigned long long h01_0 = hb.x, h23_0 = hb.y;
        unsigned long long h01_1 = hb.x, h23_1 = hb.y;
#pragma unroll
        for (int k = 0; k < CI; k++) {
            ulonglong2 w = *(const ulonglong2*)&sW1[k * 64 + j4];
            h01_0 = fma2(xp0[k], w.x, h01_0);
            h23_0 = fma2(xp0[k], w.y, h23_0);
            h01_1 = fma2(xp1[k], w.x, h01_1);
            h23_1 = fma2(xp1[k], w.y, h23_1);
        }
        float2 p00 = upk2(h01_0), p01 = upk2(h23_0);
        float2 p10 = upk2(h01_1), p11 = upk2(h23_1);
        float hv0[4] = {fmaxf(p00.x, 0.f), fmaxf(p00.y, 0.f), fmaxf(p01.x, 0.f), fmaxf(p01.y, 0.f)};
        float hv1[4] = {fmaxf(p10.x, 0.f), fmaxf(p10.y, 0.f), fmaxf(p11.x, 0.f), fmaxf(p11.y, 0.f)};
#pragma unroll
        for (int hh = 0; hh < 4; hh++) {
            unsigned long long hp0 = pk2(hv0[hh], hv0[hh]);
            unsigned long long hp1 = pk2(hv1[hh], hv1[hh]);
            const ulonglong2* wr = (const ulonglong2*)&sW2[(j4 + hh) * CO];
#pragma unroll
            for (int i = 0; i < 8; i++) {
                ulonglong2 w = wr[i];
                oa0[2 * i]     = fma2(hp0, w.x, oa0[2 * i]);
                oa0[2 * i + 1] = fma2(hp0, w.y, oa0[2 * i + 1]);
                oa1[2 * i]     = fma2(hp1, w.x, oa1[2 * i]);
                oa1[2 * i + 1] = fma2(hp1, w.y, oa1[2 * i + 1]);
            }
        }
    }
    float4* d0 = &g_Y1[((size_t)n * BT + tid) * 8];
    float4* d1 = &g_Y1[((size_t)n * BT + tid + 96) * 8];
#pragma unroll
    for (int q = 0; q < 8; q++) {
        float2 lo = upk2(oa0[2 * q]), hi = upk2(oa0[2 * q + 1]);
        d0[q] = make_float4(lo.x, lo.y, hi.x, hi.y);
        lo = upk2(oa1[2 * q]); hi = upk2(oa1[2 * q + 1]);
        d1[q] = make_float4(lo.x, lo.y, hi.x, hi.y);
    }
}

// ---------------- layer 2: grid (NN/2, 3), block 64 = 2 warps = 2 nodes ----------------
// warp w handles node blockIdx.x*2+w; lane owns rows y*64+lid and y*64+lid+32.
// 64-row slab => gather working set 82 MB, L2-resident. 2 rows/thread halves
// weight-LDS per MAC vs 1-row.
__global__ void __launch_bounds__(64) k_layer2(const float* __restrict__ W3,
                                               const float* __restrict__ b3,
                                               const float* __restrict__ W4,
                                               const float* __restrict__ b4,
                                               float* __restrict__ out) {
    __shared__ __align__(16) float sW3[CO * 128];
    __shared__ __align__(16) float sW4[128 * CO];
    __shared__ __align__(16) float sb3[128];
    __shared__ __align__(16) float sb4[CO];

    int tid = threadIdx.x;
    int wid = tid >> 5, lid = tid & 31;
    int n  = blockIdx.x * 2 + wid;
    int r0 = blockIdx.y * 64 + lid;
    int r1 = r0 + 32;
    {
        const float4* W3v = (const float4*)W3;
        const float4* W4v = (const float4*)W4;
        for (int i = tid; i < 1024; i += 64) ((float4*)sW3)[i] = W3v[i];
        for (int i = tid; i < 1024; i += 64) ((float4*)sW4)[i] = W4v[i];
        sb3[tid] = b3[tid]; sb3[64 + tid] = b3[64 + tid];
        if (tid < CO) sb4[tid] = b4[tid];
    }

    // gather rows r0, r1 (row = 8 float4); warp lanes cover 32 consecutive rows
    // = contiguous 4 KB per stream.
    const float4* Y4 = g_Y1;
    float4 A0[8], A1[8];
    size_t base0 = ((size_t)n * BT + r0) * 8;
#pragma unroll
    for (int q = 0; q < 8; q++) { A0[q] = Y4[base0 + q]; A1[q] = Y4[base0 + 256 + q]; }
    int rs = g_rowptr[n], re = g_rowptr[n + 1];
    for (int e = rs; e < re; e++) {
        size_t sb = ((size_t)g_col[e] * BT + r0) * 8;
#pragma unroll
        for (int q = 0; q < 8; q++) {
            float4 v0 = Y4[sb + q];
            float4 v1 = Y4[sb + 256 + q];
            A0[q].x += v0.x; A0[q].y += v0.y; A0[q].z += v0.z; A0[q].w += v0.w;
            A1[q].x += v1.x; A1[q].y += v1.y; A1[q].z += v1.z; A1[q].w += v1.w;
        }
    }
    float xv0[CO], xv1[CO];
#pragma unroll
    for (int q = 0; q < 8; q++) {
        xv0[4 * q + 0] = A0[q].x; xv0[4 * q + 1] = A0[q].y;
        xv0[4 * q + 2] = A0[q].z; xv0[4 * q + 3] = A0[q].w;
        xv1[4 * q + 0] = A1[q].x; xv1[4 * q + 1] = A1[q].y;
        xv1[4 * q + 2] = A1[q].z; xv1[4 * q + 3] = A1[q].w;
    }
    __syncthreads();  // weights staged

    unsigned long long oa0[16], oa1[16];
    const ulonglong2* bb = (const ulonglong2*)sb4;
#pragma unroll
    for (int i = 0; i < 8; i++) {
        ulonglong2 t2 = bb[i];
        oa0[2 * i] = t2.x; oa0[2 * i + 1] = t2.y;
        oa1[2 * i] = t2.x; oa1[2 * i + 1] = t2.y;
    }

#pragma unroll 1
    for (int j4 = 0; j4 < 128; j4 += 4) {
        ulonglong2 hb = *(const ulonglong2*)&sb3[j4];
        unsigned long long h01_0 = hb.x, h23_0 = hb.y;
        unsigned long long h01_1 = hb.x, h23_1 = hb.y;
#pragma unroll
        for (int k = 0; k < CO; k++) {
            ulonglong2 w = *(const ulonglong2*)&sW3[k * 128 + j4];
            unsigned long long xp0 = pk2(xv0[k], xv0[k]);
            unsigned long long xp1 = pk2(xv1[k], xv1[k]);
            h01_0 = fma2(xp0, w.x, h01_0);
            h23_0 = fma2(xp0, w.y, h23_0);
            h01_1 = fma2(xp1, w.x, h01_1);
            h23_1 = fma2(xp1, w.y, h23_1);
        }
        float2 p00 = upk2(h01_0), p01 = upk2(h23_0);
        float2 p10 = upk2(h01_1), p11 = upk2(h23_1);
        float hv0[4] = {fmaxf(p00.x, 0.f), fmaxf(p00.y, 0.f), fmaxf(p01.x, 0.f), fmaxf(p01.y, 0.f)};
        float hv1[4] = {fmaxf(p10.x, 0.f), fmaxf(p10.y, 0.f), fmaxf(p11.x, 0.f), fmaxf(p11.y, 0.f)};
#pragma unroll
        for (int hh = 0; hh < 4; hh++) {
            unsigned long long hp0 = pk2(hv0[hh], hv0[hh]);
            unsigned long long hp1 = pk2(hv1[hh], hv1[hh]);
            const ulonglong2* wr = (const ulonglong2*)&sW4[(j4 + hh) * CO];
#pragma unroll
            for (int i = 0; i < 8; i++) {
                ulonglong2 w = wr[i];
                oa0[2 * i]     = fma2(hp0, w.x, oa0[2 * i]);
                oa0[2 * i + 1] = fma2(hp0, w.y, oa0[2 * i + 1]);
                oa1[2 * i]     = fma2(hp1, w.x, oa1[2 * i]);
                oa1[2 * i + 1] = fma2(hp1, w.y, oa1[2 * i + 1]);
            }
        }
    }

    // final relu + direct transposed write: row r -> (b = r/24, t = r%24)
    {
        int b = r0 / TT, t = r0 % TT;
        size_t obase = ((size_t)(b * NN + n) * CO) * TT + t;
#pragma unroll
        for (int q = 0; q < 16; q++) {
            float2 p = upk2(oa0[q]);
            out[obase + (size_t)(2 * q) * TT]     = fmaxf(p.x, 0.f);
            out[obase + (size_t)(2 * q + 1) * TT] = fmaxf(p.y, 0.f);
        }
    }
    {
        int b = r1 / TT, t = r1 % TT;
        size_t obase = ((size_t)(b * NN + n) * CO) * TT + t;
#pragma unroll
        for (int q = 0; q < 16; q++) {
            float2 p = upk2(oa1[q]);
            out[obase + (size_t)(2 * q) * TT]     = fmaxf(p.x, 0.f);
            out[obase + (size_t)(2 * q + 1) * TT] = fmaxf(p.y, 0.f);
        }
    }
}

// ---------------- launch ----------------
extern "C" void kernel_launch(void* const* d_in, const int* in_sizes, int n_in,
                              void* d_out, int out_size) {
    const float* x  = (const float*)d_in[0];
    const void*  ei = d_in[1];
    const float* W1 = (const float*)d_in[2];
    const float* b1 = (const float*)d_in[3];
    const float* W2 = (const float*)d_in[4];
    const float* b2 = (const float*)d_in[5];
    const float* W3 = (const float*)d_in[6];
    const float* b3 = (const float*)d_in[7];
    const float* W4 = (const float*)d_in[8];
    const float* b4 = (const float*)d_in[9];
    float* out = (float*)d_out;

    k_prep<<<1, 1024>>>(ei);
    k_fill<<<(NE + 255) / 256, 256>>>(ei);
    k_transpose<<<NN, 256>>>(x);
    k_layer1<<<NN, 96>>>(W1, b1, W2, b2);
    k_layer2<<<dim3(NN / 2, 3), 64>>>(W3, b3, W4, b4, out);
}